// round 13
// baseline (speedup 1.0000x reference)
#include <cuda_runtime.h>
#include <cooperative_groups.h>
#include <cstdint>

namespace cg = cooperative_groups;

// ---------------- problem dims ----------------
#define BB 512
#define TT 64
#define HH 256     // hidden / obs dim
#define AA 6       // action dim
#define RR 256     // recurrent dim
#define KG 768     // 3*RR gate dim
#define LL 1024    // latent dim
#define NCTA 128   // CTAs (64 clusters of 2); each cluster owns 8 rows, each CTA owns 4

// output layout: [deter | stoch | logits]
#define DET_OFF 0
#define ST_OFF  (BB * TT * RR)
#define LG_OFF  (BB * TT * RR + BB * TT * LL)

// ---------------- device scratch ----------------
__device__ __align__(16) float g_WcT[LL * KG];     // [c][k] fused stoch weights
__device__ __align__(16) float g_WcaT[AA * KG];    // [j][k] fused action weights
__device__ __align__(16) float g_bc[KG];           // b_ih + W_ih @ b_in
__device__ __align__(16) float g_WhhT[RR * KG];    // [j][k]
__device__ __align__(16) float g_WphT[RR * LL];    // [j][l]
__device__ __align__(16) float g_WpoT[HH * LL];    // [k][n]

// ---------------- packed fp32 helpers (FFMA2 path) ----------------
__device__ __forceinline__ void ffma2(float2& d, const float2 a, const float2 b) {
    asm("fma.rn.f32x2 %0, %1, %2, %0;"
        : "+l"(reinterpret_cast<unsigned long long&>(d))
        : "l"(reinterpret_cast<const unsigned long long&>(a)),
          "l"(reinterpret_cast<const unsigned long long&>(b)));
}

// ---------------- merged prep: fuse-GEMM + transposes in one launch ----------------
// blocks [0,204):   C[c][k] = sum_h W_in[h][c] * W_ih[k][h]   (64x64 tiles, BK=16)
// blocks [204,396): W_hh [768][256]  -> g_WhhT [256][768]
// blocks [396,908): W_post [1024][512] -> g_WphT [256][1024] / g_WpoT [256][1024]
__global__ void __launch_bounds__(256) prep_all(const float* __restrict__ W_in,
                                                const float* __restrict__ b_in,
                                                const float* __restrict__ W_ih,
                                                const float* __restrict__ b_ih,
                                                const float* __restrict__ W_hh,
                                                const float* __restrict__ W_post) {
    __shared__ float sh[2 * 16 * 65];      // fuse: As|Bs.  transpose: tile[32][33]
    const int tid = threadIdx.x;
    const int bid = blockIdx.x;

    if (bid < 204) {
        float (*As)[65] = (float(*)[65])sh;
        float (*Bs)[65] = (float(*)[65])(sh + 16 * 65);
        const int bk = (bid % 12) * 64;
        const int bc = (bid / 12) * 64;
        const int tyc = tid >> 4;
        const int txk = tid & 15;
        float acc[4][4];
        #pragma unroll
        for (int i = 0; i < 4; ++i)
            #pragma unroll
            for (int j = 0; j < 4; ++j) acc[i][j] = 0.f;

        for (int k0 = 0; k0 < HH; k0 += 16) {
            #pragma unroll
            for (int i = 0; i < 4; ++i) {
                int e = tid + i * 256;
                int kk = e >> 6, cc = e & 63;
                int c = bc + cc;
                float v = 0.f;
                if (c < 1030)       v = W_in[(size_t)(k0 + kk) * 1030 + c];
                else if (c == 1030) v = b_in[k0 + kk];
                As[kk][cc] = v;
            }
            #pragma unroll
            for (int i = 0; i < 4; ++i) {
                int e = tid + i * 256;
                int kn = e >> 4, kk = e & 15;
                Bs[kk][kn] = W_ih[(size_t)(bk + kn) * HH + k0 + kk];
            }
            __syncthreads();
            #pragma unroll
            for (int kk = 0; kk < 16; ++kk) {
                float a[4], b[4];
                #pragma unroll
                for (int i = 0; i < 4; ++i) a[i] = As[kk][tyc * 4 + i];
                #pragma unroll
                for (int j = 0; j < 4; ++j) b[j] = Bs[kk][txk * 4 + j];
                #pragma unroll
                for (int i = 0; i < 4; ++i)
                    #pragma unroll
                    for (int j = 0; j < 4; ++j)
                        acc[i][j] = fmaf(a[i], b[j], acc[i][j]);
            }
            __syncthreads();
        }
        #pragma unroll
        for (int i = 0; i < 4; ++i) {
            int c = bc + tyc * 4 + i;
            int k = bk + txk * 4;
            if (c < LL) {
                *(float4*)&g_WcT[(size_t)c * KG + k] =
                    make_float4(acc[i][0], acc[i][1], acc[i][2], acc[i][3]);
            } else if (c < 1030) {
                *(float4*)&g_WcaT[(size_t)(c - LL) * KG + k] =
                    make_float4(acc[i][0], acc[i][1], acc[i][2], acc[i][3]);
            } else if (c == 1030) {
                float4 bi = *(const float4*)&b_ih[k];
                g_bc[k + 0] = acc[i][0] + bi.x;
                g_bc[k + 1] = acc[i][1] + bi.y;
                g_bc[k + 2] = acc[i][2] + bi.z;
                g_bc[k + 3] = acc[i][3] + bi.w;
            }
        }
    } else {
        float (*tile)[33] = (float(*)[33])sh;
        const int tx = tid & 31;
        const int ty0 = tid >> 5;
        if (bid < 396) {
            int r = bid - 204;
            int row0 = (r % 24) * 32;
            int col0 = (r / 24) * 32;
            #pragma unroll
            for (int rr = 0; rr < 4; ++rr) {
                int row = ty0 + rr * 8;
                tile[row][tx] = W_hh[(size_t)(row0 + row) * RR + col0 + tx];
            }
            __syncthreads();
            #pragma unroll
            for (int rr = 0; rr < 4; ++rr) {
                int row = ty0 + rr * 8;
                g_WhhT[(size_t)(col0 + row) * KG + row0 + tx] = tile[tx][row];
            }
        } else {
            int r = bid - 396;
            int row0 = (r % 32) * 32;
            int col0 = (r / 32) * 32;
            #pragma unroll
            for (int rr = 0; rr < 4; ++rr) {
                int row = ty0 + rr * 8;
                tile[row][tx] = W_post[(size_t)(row0 + row) * (RR + HH) + col0 + tx];
            }
            __syncthreads();
            #pragma unroll
            for (int rr = 0; rr < 4; ++rr) {
                int row = ty0 + rr * 8;
                int m = col0 + row;
                float v = tile[tx][row];
                if (m < RR) g_WphT[(size_t)m * LL + row0 + tx] = v;
                else        g_WpoT[(size_t)(m - RR) * LL + row0 + tx] = v;
            }
        }
    }
}

// ---------------- obs GEMM: 128x128, BK=16, double-buffered, 8x8 microtile, f32x2 ----------------
// out_logits[m][n] = b_post[n] + obs[m]·W_po[n].  M=32768, N=1024, K=256.
__global__ void __launch_bounds__(256) obs_gemm(const float* __restrict__ obs,
                                                const float* __restrict__ b_post,
                                                float* __restrict__ outL) {
    __shared__ float2 As2[2][16][128];   // duplicated {a,a}  32 KB
    __shared__ float  Bs[2][16][128];    // 16 KB
    const int tid = threadIdx.x;
    const int bm = blockIdx.y * 128;
    const int bn = blockIdx.x * 128;
    const int ty = tid >> 4;             // m microtile
    const int tx = tid & 15;             // n microtile
    // A-load mapping (2 float4/thread): f -> row = f>>2, kq = (f&3)*4
    const int ar0 = tid >> 2,          akq0 = (tid & 3) * 4;
    const int ar1 = (tid + 256) >> 2,  akq1 = ((tid + 256) & 3) * 4;
    // B-load mapping (2 float4/thread): e -> kk = e>>5, n4 = (e&31)*4
    const int bkk0 = tid >> 5,         bnn0 = (tid & 31) * 4;
    const int bkk1 = (tid + 256) >> 5, bnn1 = ((tid + 256) & 31) * 4;

    float2 acc[8][4];
    #pragma unroll
    for (int i = 0; i < 8; ++i)
        #pragma unroll
        for (int j = 0; j < 4; ++j) acc[i][j] = make_float2(0.f, 0.f);

    // prologue: load k0 = 0 into stage 0
    float4 va0 = *(const float4*)&obs[(size_t)(bm + ar0) * HH + akq0];
    float4 va1 = *(const float4*)&obs[(size_t)(bm + ar1) * HH + akq1];
    float4 vb0 = *(const float4*)&g_WpoT[(size_t)bkk0 * LL + bn + bnn0];
    float4 vb1 = *(const float4*)&g_WpoT[(size_t)bkk1 * LL + bn + bnn1];
    As2[0][akq0 + 0][ar0] = make_float2(va0.x, va0.x);
    As2[0][akq0 + 1][ar0] = make_float2(va0.y, va0.y);
    As2[0][akq0 + 2][ar0] = make_float2(va0.z, va0.z);
    As2[0][akq0 + 3][ar0] = make_float2(va0.w, va0.w);
    As2[0][akq1 + 0][ar1] = make_float2(va1.x, va1.x);
    As2[0][akq1 + 1][ar1] = make_float2(va1.y, va1.y);
    As2[0][akq1 + 2][ar1] = make_float2(va1.z, va1.z);
    As2[0][akq1 + 3][ar1] = make_float2(va1.w, va1.w);
    *(float4*)&Bs[0][bkk0][bnn0] = vb0;
    *(float4*)&Bs[0][bkk1][bnn1] = vb1;
    __syncthreads();

    #pragma unroll 1
    for (int k0 = 0; k0 < HH; k0 += 16) {
        const int st = (k0 >> 4) & 1;
        const bool has_next = (k0 + 16) < HH;
        if (has_next) {
            va0 = *(const float4*)&obs[(size_t)(bm + ar0) * HH + k0 + 16 + akq0];
            va1 = *(const float4*)&obs[(size_t)(bm + ar1) * HH + k0 + 16 + akq1];
            vb0 = *(const float4*)&g_WpoT[(size_t)(k0 + 16 + bkk0) * LL + bn + bnn0];
            vb1 = *(const float4*)&g_WpoT[(size_t)(k0 + 16 + bkk1) * LL + bn + bnn1];
        }
        const float2 (*A)[128] = As2[st];
        const float  (*B)[128] = Bs[st];
        #pragma unroll
        for (int kk = 0; kk < 16; ++kk) {
            float2 a[8];
            *(float4*)&a[0] = *(const float4*)&A[kk][ty * 8 + 0];
            *(float4*)&a[2] = *(const float4*)&A[kk][ty * 8 + 2];
            *(float4*)&a[4] = *(const float4*)&A[kk][ty * 8 + 4];
            *(float4*)&a[6] = *(const float4*)&A[kk][ty * 8 + 6];
            float b[8];
            *(float4*)&b[0] = *(const float4*)&B[kk][tx * 8 + 0];
            *(float4*)&b[4] = *(const float4*)&B[kk][tx * 8 + 4];
            float2 b2[4] = { make_float2(b[0], b[1]), make_float2(b[2], b[3]),
                             make_float2(b[4], b[5]), make_float2(b[6], b[7]) };
            #pragma unroll
            for (int i = 0; i < 8; ++i)
                #pragma unroll
                for (int j = 0; j < 4; ++j)
                    ffma2(acc[i][j], a[i], b2[j]);
        }
        if (has_next) {
            const int ns = st ^ 1;
            As2[ns][akq0 + 0][ar0] = make_float2(va0.x, va0.x);
            As2[ns][akq0 + 1][ar0] = make_float2(va0.y, va0.y);
            As2[ns][akq0 + 2][ar0] = make_float2(va0.z, va0.z);
            As2[ns][akq0 + 3][ar0] = make_float2(va0.w, va0.w);
            As2[ns][akq1 + 0][ar1] = make_float2(va1.x, va1.x);
            As2[ns][akq1 + 1][ar1] = make_float2(va1.y, va1.y);
            As2[ns][akq1 + 2][ar1] = make_float2(va1.z, va1.z);
            As2[ns][akq1 + 3][ar1] = make_float2(va1.w, va1.w);
            *(float4*)&Bs[ns][bkk0][bnn0] = vb0;
            *(float4*)&Bs[ns][bkk1][bnn1] = vb1;
            __syncthreads();
        }
    }

    const int nb = bn + tx * 8;
    float4 bpA = *(const float4*)&b_post[nb];
    float4 bpB = *(const float4*)&b_post[nb + 4];
    #pragma unroll
    for (int i = 0; i < 8; ++i) {
        int m = bm + ty * 8 + i;
        float4 v0, v1;
        v0.x = acc[i][0].x + bpA.x; v0.y = acc[i][0].y + bpA.y;
        v0.z = acc[i][1].x + bpA.z; v0.w = acc[i][1].y + bpA.w;
        v1.x = acc[i][2].x + bpB.x; v1.y = acc[i][2].y + bpB.y;
        v1.z = acc[i][3].x + bpB.z; v1.w = acc[i][3].y + bpB.w;
        *(float4*)&outL[(size_t)m * LL + nb]     = v0;
        *(float4*)&outL[(size_t)m * LL + nb + 4] = v1;
    }
}

// ---------------- cluster-2 persistent scan (round-9/11 proven version, verbatim) ----------------
#define OFF_GI     0
#define OFF_GH8    3072
#define OFF_GHR    9216
#define OFF_DET8   12288
#define OFF_DETOWN 16384
#define OFF_LG8    18432
#define OFF_LGR    26624
#define SMEM_FLOATS 30720

__global__ void __launch_bounds__(512, 1) __cluster_dims__(2, 1, 1)
scan_kernel(const float* __restrict__ action,
            const unsigned int* __restrict__ first,
            const float* __restrict__ gumbel,       // [T][B][1024]
            const float* __restrict__ b_hh,
            float* __restrict__ out) {

    extern __shared__ float smem[];
    float* s_gi     = smem + OFF_GI;
    float* s_gh8    = smem + OFF_GH8;
    float* s_ghr    = smem + OFF_GHR;
    float* s_det8   = smem + OFF_DET8;
    float* s_detown = smem + OFF_DETOWN;
    float* s_lg8    = smem + OFF_LG8;
    float* s_lgr    = smem + OFF_LGR;
    __shared__ int   s_idx[4][32];
    __shared__ float s_act[4][AA];
    __shared__ int   s_reset[8];     // pair-global rows, first[t]

    cg::cluster_group cluster = cg::this_cluster();
    const int rank = (int)cluster.block_rank();
    float* p_ghr  = (float*)cluster.map_shared_rank(s_ghr,  rank ^ 1);
    float* p_det8 = (float*)cluster.map_shared_rank(s_det8, rank ^ 1);
    float* p_lgr  = (float*)cluster.map_shared_rank(s_lgr,  rank ^ 1);

    const int tid = threadIdx.x;
    const int jh  = tid >> 8;        // intra-CTA jj-half
    const int lk  = tid & 255;
    const int pair  = blockIdx.x >> 1;
    const int prow0 = pair * 8;
    const int orow0 = prow0 + rank * 4;      // own rows base
    const int Jbase = rank * 128;            // this CTA's j slice
    int cur = 0;

    for (int t = 0; t < TT; ++t) {
        // ---- flags (all 8 rows) + action (own rows) ----
        if (tid < 8) {
            unsigned f = first[(prow0 + tid) * TT + t];
            s_reset[tid] = (t == 0) || (f != 0u);
        }
        if (tid >= 32 && tid < 32 + 4 * AA) {
            int e = tid - 32;
            s_act[e / AA][e % AA] = action[((size_t)(orow0 + e / AA) * TT + t) * AA + (e % AA)];
        }
        __syncthreads();

        // ---- zero carries on reset (det8 slice: all 8 rows; detown: own rows) ----
        #pragma unroll
        for (int k = 0; k < 2; ++k) {
            int idx = tid + k * 512;       // 1024 items: det8 slice
            int jj = idx >> 3, g = idx & 7;
            if (s_reset[g])
                *(float2*)&s_det8[cur * 2048 + jj * 16 + 2 * g] = make_float2(0.f, 0.f);
        }
        #pragma unroll
        for (int k = 0; k < 2; ++k) {
            int idx = tid + k * 512;       // 1024 items: detown
            int r = idx >> 8, u = idx & 255;
            if (s_reset[rank * 4 + r])
                s_detown[cur * 1024 + r * 256 + u] = 0.f;
        }
        __syncthreads();

        // ---- gi for own rows (bias + action + one-hot gather) ----
        for (int item = tid; item < 4 * 192; item += 512) {
            int r = item / 192;
            int q = (item % 192) * 4;
            float4 a4 = *(const float4*)&g_bc[q];
            #pragma unroll
            for (int j = 0; j < AA; ++j) {
                float av = s_act[r][j];
                float4 w = *(const float4*)&g_WcaT[j * KG + q];
                a4.x = fmaf(av, w.x, a4.x); a4.y = fmaf(av, w.y, a4.y);
                a4.z = fmaf(av, w.z, a4.z); a4.w = fmaf(av, w.w, a4.w);
            }
            if (!s_reset[rank * 4 + r]) {
                #pragma unroll 8
                for (int g = 0; g < 32; ++g) {
                    int c = (g << 5) + s_idx[r][g];
                    float4 w = *(const float4*)&g_WcT[c * KG + q];
                    a4.x += w.x; a4.y += w.y; a4.z += w.z; a4.w += w.w;
                }
            }
            *(float4*)&s_gi[r * KG + q] = a4;
        }

        // ---- phase 1: gh partial over my j-slice (8-deep weight prefetch) ----
        float2 gh[8][2];
        if (lk < 192) {
            const int q4 = lk * 4;
            if (rank == 0 && jh == 0) {
                float4 bh = *(const float4*)&b_hh[q4];
                #pragma unroll
                for (int g = 0; g < 8; ++g) {
                    gh[g][0] = make_float2(bh.x, bh.y);
                    gh[g][1] = make_float2(bh.z, bh.w);
                }
            } else {
                #pragma unroll
                for (int g = 0; g < 8; ++g) {
                    gh[g][0] = make_float2(0.f, 0.f);
                    gh[g][1] = make_float2(0.f, 0.f);
                }
            }
            const float4* wp  = (const float4*)&g_WhhT[(size_t)(Jbase + jh * 64) * KG + q4];
            const size_t  WS  = KG / 4;
            const float4* db4 = (const float4*)(s_det8 + cur * 2048 + (jh * 64) * 16);
            float4 wb8[8];
            #pragma unroll
            for (int p = 0; p < 8; ++p) wb8[p] = wp[(size_t)p * WS];
            #pragma unroll 1
            for (int base = 0; base < 64; base += 8) {
                #pragma unroll
                for (int p = 0; p < 8; ++p) {
                    float4 w = wb8[p];
                    int nj = base + 8 + p; nj = (nj < 64) ? nj : 63;
                    wb8[p] = wp[(size_t)nj * WS];
                    const float4* dq = db4 + (size_t)(base + p) * 4;
                    float4 dA = dq[0], dB = dq[1], dC = dq[2], dD = dq[3];
                    float2 wl = make_float2(w.x, w.y), wh2 = make_float2(w.z, w.w);
                    float2 dp[8] = { make_float2(dA.x, dA.y), make_float2(dA.z, dA.w),
                                     make_float2(dB.x, dB.y), make_float2(dB.z, dB.w),
                                     make_float2(dC.x, dC.y), make_float2(dC.z, dC.w),
                                     make_float2(dD.x, dD.y), make_float2(dD.z, dD.w) };
                    #pragma unroll
                    for (int g = 0; g < 8; ++g) {
                        ffma2(gh[g][0], dp[g], wl);
                        ffma2(gh[g][1], dp[g], wh2);
                    }
                }
            }
            if (jh == 0) {
                #pragma unroll
                for (int g = 0; g < 8; ++g)
                    *(float4*)&s_gh8[g * KG + q4] =
                        make_float4(gh[g][0].x, gh[g][0].y, gh[g][1].x, gh[g][1].y);
            }
        }
        __syncthreads();
        if (jh == 1 && lk < 192) {   // combine halves; push peer rows to peer's s_ghr
            const int q4 = lk * 4;
            const int pb = (rank ^ 1) * 4;
            #pragma unroll
            for (int g = 0; g < 8; ++g) {
                float4 p = *(const float4*)&s_gh8[g * KG + q4];
                float4 c = make_float4(p.x + gh[g][0].x, p.y + gh[g][0].y,
                                       p.z + gh[g][1].x, p.w + gh[g][1].y);
                *(float4*)&s_gh8[g * KG + q4] = c;
                if (g >= pb && g < pb + 4)
                    *(float4*)&p_ghr[(g - pb) * KG + q4] = c;
            }
        }
        cluster.sync();   // CS1: gh partials exchanged

        // ---- GRU for own rows + det distribution ----
        {
            const int u = lk;
            #pragma unroll
            for (int ii = 0; ii < 2; ++ii) {
                int i = jh * 2 + ii;          // own-local row
                int g = rank * 4 + i;         // pair-global row
                float ir = s_gi[i * KG + u];
                float hr = s_gh8[g * KG + u]       + s_ghr[i * KG + u];
                float iz = s_gi[i * KG + u + 256];
                float hz = s_gh8[g * KG + u + 256] + s_ghr[i * KG + u + 256];
                float in_ = s_gi[i * KG + u + 512];
                float hn = s_gh8[g * KG + u + 512] + s_ghr[i * KG + u + 512];
                float rg = 1.f / (1.f + expf(-(ir + hr)));
                float z  = 1.f / (1.f + expf(-(iz + hz)));
                float n  = tanhf(fmaf(rg, hn, in_));
                float dp = s_detown[cur * 1024 + i * 256 + u];
                float h  = (1.f - z) * n + z * dp;
                s_detown[(cur ^ 1) * 1024 + i * 256 + u] = h;
                float2 hh = make_float2(h, h);
                int jloc = u & 127;
                if ((u >> 7) == rank)
                    *(float2*)&s_det8[(cur ^ 1) * 2048 + jloc * 16 + 2 * g] = hh;
                else
                    *(float2*)&p_det8[(cur ^ 1) * 2048 + jloc * 16 + 2 * g] = hh;
                out[DET_OFF + ((size_t)(orow0 + i) * TT + t) * RR + u] = h;
            }
        }
        cluster.sync();   // CS2: new det slices exchanged

        // ---- phase 2: logits partial over my j-slice (8-deep weight prefetch) ----
        float2 acc[8][2];
        {
            const int q4 = lk * 4;
            #pragma unroll
            for (int g = 0; g < 8; ++g) {
                acc[g][0] = make_float2(0.f, 0.f);
                acc[g][1] = make_float2(0.f, 0.f);
            }
            const float4* wp  = (const float4*)&g_WphT[(size_t)(Jbase + jh * 64) * LL + q4];
            const size_t  WS  = LL / 4;
            const float4* db4 = (const float4*)(s_det8 + (cur ^ 1) * 2048 + (jh * 64) * 16);
            float4 wb8[8];
            #pragma unroll
            for (int p = 0; p < 8; ++p) wb8[p] = wp[(size_t)p * WS];
            #pragma unroll 1
            for (int base = 0; base < 64; base += 8) {
                #pragma unroll
                for (int p = 0; p < 8; ++p) {
                    float4 w = wb8[p];
                    int nj = base + 8 + p; nj = (nj < 64) ? nj : 63;
                    wb8[p] = wp[(size_t)nj * WS];
                    const float4* dq = db4 + (size_t)(base + p) * 4;
                    float4 dA = dq[0], dB = dq[1], dC = dq[2], dD = dq[3];
                    float2 wl = make_float2(w.x, w.y), wh2 = make_float2(w.z, w.w);
                    float2 dp[8] = { make_float2(dA.x, dA.y), make_float2(dA.z, dA.w),
                                     make_float2(dB.x, dB.y), make_float2(dB.z, dB.w),
                                     make_float2(dC.x, dC.y), make_float2(dC.z, dC.w),
                                     make_float2(dD.x, dD.y), make_float2(dD.z, dD.w) };
                    #pragma unroll
                    for (int g = 0; g < 8; ++g) {
                        ffma2(acc[g][0], dp[g], wl);
                        ffma2(acc[g][1], dp[g], wh2);
                    }
                }
            }
            if (jh == 0) {
                #pragma unroll
                for (int g = 0; g < 8; ++g)
                    *(float4*)&s_lg8[g * LL + q4] =
                        make_float4(acc[g][0].x, acc[g][0].y, acc[g][1].x, acc[g][1].y);
            }
        }
        __syncthreads();
        if (jh == 1) {
            const int q4 = lk * 4;
            const int pb = (rank ^ 1) * 4;
            #pragma unroll
            for (int g = 0; g < 8; ++g) {
                float4 p = *(const float4*)&s_lg8[g * LL + q4];
                float4 c = make_float4(p.x + acc[g][0].x, p.y + acc[g][0].y,
                                       p.z + acc[g][1].x, p.w + acc[g][1].y);
                *(float4*)&s_lg8[g * LL + q4] = c;
                if (g >= pb && g < pb + 4)
                    *(float4*)&p_lgr[(g - pb) * LL + q4] = c;
            }
        }
        cluster.sync();   // CS3: logits partials exchanged

        // ---- finalize own rows: logits, gumbel argmax, one-hot stoch ----
        {
            const int q4 = lk * 4;
            #pragma unroll
            for (int ii = 0; ii < 2; ++ii) {
                int i = jh * 2 + ii;
                int g = rank * 4 + i;
                size_t bt = (size_t)(orow0 + i) * TT + t;
                float4 ob = *(const float4*)&out[LG_OFF + bt * LL + q4];  // obs part + b_post
                float4 pa = *(const float4*)&s_lg8[g * LL + q4];
                float4 pbv = *(const float4*)&s_lgr[i * LL + q4];
                float4 lg;
                lg.x = ob.x + pa.x + pbv.x; lg.y = ob.y + pa.y + pbv.y;
                lg.z = ob.z + pa.z + pbv.z; lg.w = ob.w + pa.w + pbv.w;
                *(float4*)&out[LG_OFF + bt * LL + q4] = lg;
                float4 g4 = *(const float4*)&gumbel[((size_t)t * BB + orow0 + i) * LL + q4];
                float v0 = lg.x + g4.x, v1 = lg.y + g4.y;
                float v2 = lg.z + g4.z, v3 = lg.w + g4.w;
                float bv = v0; int bi = q4;
                if (v1 > bv) { bv = v1; bi = q4 + 1; }
                if (v2 > bv) { bv = v2; bi = q4 + 2; }
                if (v3 > bv) { bv = v3; bi = q4 + 3; }
                #pragma unroll
                for (int off = 1; off < 8; off <<= 1) {
                    float ov = __shfl_xor_sync(0xffffffffu, bv, off);
                    int   oi = __shfl_xor_sync(0xffffffffu, bi, off);
                    if (ov > bv || (ov == bv && oi < bi)) { bv = ov; bi = oi; }
                }
                float4 sv;
                sv.x = (q4 + 0 == bi) ? 1.f : 0.f;
                sv.y = (q4 + 1 == bi) ? 1.f : 0.f;
                sv.z = (q4 + 2 == bi) ? 1.f : 0.f;
                sv.w = (q4 + 3 == bi) ? 1.f : 0.f;
                *(float4*)&out[ST_OFF + bt * LL + q4] = sv;
                if ((lk & 7) == 0) s_idx[i][lk >> 3] = bi & 31;
            }
        }
        cur ^= 1;
    }
}

// ---------------- launcher ----------------
extern "C" void kernel_launch(void* const* d_in, const int* in_sizes, int n_in,
                              void* d_out, int out_size) {
    const float* obs          = (const float*)d_in[0];
    const float* action       = (const float*)d_in[1];
    const unsigned int* first = (const unsigned int*)d_in[2];
    const float* gumbel       = (const float*)d_in[3];
    const float* W_in         = (const float*)d_in[4];
    const float* b_in         = (const float*)d_in[5];
    const float* W_ih         = (const float*)d_in[6];
    const float* W_hh         = (const float*)d_in[7];
    const float* b_ih         = (const float*)d_in[8];
    const float* b_hh         = (const float*)d_in[9];
    const float* W_post       = (const float*)d_in[10];
    const float* b_post       = (const float*)d_in[11];
    float* out = (float*)d_out;
    (void)in_sizes; (void)n_in; (void)out_size;

    static int smem_set = 0;
    if (!smem_set) {
        cudaFuncSetAttribute(scan_kernel, cudaFuncAttributeMaxDynamicSharedMemorySize,
                             SMEM_FLOATS * sizeof(float));
        smem_set = 1;
    }

    prep_all<<<908, 256>>>(W_in, b_in, W_ih, b_ih, W_hh, W_post);
    dim3 ggrid(LL / 128, (BB * TT) / 128);
    obs_gemm<<<ggrid, 256>>>(obs, b_post, out + LG_OFF);
    scan_kernel<<<NCTA, 512, SMEM_FLOATS * sizeof(float)>>>(action, first, gumbel, b_hh, out);
}

// round 14
// speedup vs baseline: 1.9064x; 1.9064x over previous
#include <cuda_runtime.h>
#include <cooperative_groups.h>
#include <cstdint>

namespace cg = cooperative_groups;

// ---------------- problem dims ----------------
#define BB 512
#define TT 64
#define HH 256     // hidden / obs dim
#define AA 6       // action dim
#define RR 256     // recurrent dim
#define KG 768     // 3*RR gate dim
#define LL 1024    // latent dim
#define NCTA 128   // CTAs (64 clusters of 2); each cluster owns 8 rows, each CTA owns 4

// output layout: [deter | stoch | logits]
#define DET_OFF 0
#define ST_OFF  (BB * TT * RR)
#define LG_OFF  (BB * TT * RR + BB * TT * LL)

// ---------------- device scratch ----------------
__device__ __align__(16) float g_WcT[LL * KG];     // [c][k] fused stoch weights
__device__ __align__(16) float g_WcaT[AA * KG];    // [j][k] fused action weights
__device__ __align__(16) float g_bc[KG];           // b_ih + W_ih @ b_in
__device__ __align__(16) float g_WhhT[RR * KG];    // [j][k]
__device__ __align__(16) float g_WphT[RR * LL];    // [j][l]
__device__ __align__(16) float g_WpoT[HH * LL];    // [k][n]

// ---------------- packed fp32 helpers (FFMA2 path) ----------------
__device__ __forceinline__ void ffma2(float2& d, const float2 a, const float2 b) {
    asm("fma.rn.f32x2 %0, %1, %2, %0;"
        : "+l"(reinterpret_cast<unsigned long long&>(d))
        : "l"(reinterpret_cast<const unsigned long long&>(a)),
          "l"(reinterpret_cast<const unsigned long long&>(b)));
}

// ---------------- prep 1: fused GEMM  C[c][k] = sum_h W_in[h][c] * W_ih[k][h] ----------------
__global__ void __launch_bounds__(256) prep_fuse(const float* __restrict__ W_in,
                                                 const float* __restrict__ b_in,
                                                 const float* __restrict__ W_ih,
                                                 const float* __restrict__ b_ih) {
    __shared__ float As[16][64 + 1];
    __shared__ float Bs[16][64 + 1];
    const int tid = threadIdx.x;
    const int bk = blockIdx.x * 64;
    const int bc = blockIdx.y * 64;
    const int tyc = tid >> 4;
    const int txk = tid & 15;

    float acc[4][4];
    #pragma unroll
    for (int i = 0; i < 4; ++i)
        #pragma unroll
        for (int j = 0; j < 4; ++j) acc[i][j] = 0.f;

    for (int k0 = 0; k0 < HH; k0 += 16) {
        #pragma unroll
        for (int i = 0; i < 4; ++i) {
            int e = tid + i * 256;
            int kk = e >> 6, cc = e & 63;
            int c = bc + cc;
            float v = 0.f;
            if (c < 1030)       v = W_in[(size_t)(k0 + kk) * 1030 + c];
            else if (c == 1030) v = b_in[k0 + kk];
            As[kk][cc] = v;
        }
        #pragma unroll
        for (int i = 0; i < 4; ++i) {
            int e = tid + i * 256;
            int kn = e >> 4, kk = e & 15;
            Bs[kk][kn] = W_ih[(size_t)(bk + kn) * HH + k0 + kk];
        }
        __syncthreads();
        #pragma unroll
        for (int kk = 0; kk < 16; ++kk) {
            float a[4], b[4];
            #pragma unroll
            for (int i = 0; i < 4; ++i) a[i] = As[kk][tyc * 4 + i];
            #pragma unroll
            for (int j = 0; j < 4; ++j) b[j] = Bs[kk][txk * 4 + j];
            #pragma unroll
            for (int i = 0; i < 4; ++i)
                #pragma unroll
                for (int j = 0; j < 4; ++j)
                    acc[i][j] = fmaf(a[i], b[j], acc[i][j]);
        }
        __syncthreads();
    }
    #pragma unroll
    for (int i = 0; i < 4; ++i) {
        int c = bc + tyc * 4 + i;
        int k = bk + txk * 4;
        if (c < LL) {
            *(float4*)&g_WcT[(size_t)c * KG + k] =
                make_float4(acc[i][0], acc[i][1], acc[i][2], acc[i][3]);
        } else if (c < 1030) {
            *(float4*)&g_WcaT[(size_t)(c - LL) * KG + k] =
                make_float4(acc[i][0], acc[i][1], acc[i][2], acc[i][3]);
        } else if (c == 1030) {
            float4 bi = *(const float4*)&b_ih[k];
            g_bc[k + 0] = acc[i][0] + bi.x;
            g_bc[k + 1] = acc[i][1] + bi.y;
            g_bc[k + 2] = acc[i][2] + bi.z;
            g_bc[k + 3] = acc[i][3] + bi.w;
        }
    }
}

// ---------------- prep 2: tiled transposes ----------------
__global__ void __launch_bounds__(256) prep_transpose(const float* __restrict__ W_hh,
                                                      const float* __restrict__ W_post) {
    __shared__ float tile[32][33];
    const int tid = threadIdx.x;
    const int tx = tid & 31;
    const int ty0 = tid >> 5;
    const int z = blockIdx.z;
    const int row0 = blockIdx.x * 32;
    const int col0 = blockIdx.y * 32;

    if (z == 0) {
        if (blockIdx.x >= 24 || blockIdx.y >= 8) return;
        #pragma unroll
        for (int r = 0; r < 4; ++r) {
            int row = ty0 + r * 8;
            tile[row][tx] = W_hh[(size_t)(row0 + row) * RR + col0 + tx];
        }
        __syncthreads();
        #pragma unroll
        for (int r = 0; r < 4; ++r) {
            int row = ty0 + r * 8;
            g_WhhT[(size_t)(col0 + row) * KG + row0 + tx] = tile[tx][row];
        }
    } else {
        #pragma unroll
        for (int r = 0; r < 4; ++r) {
            int row = ty0 + r * 8;
            tile[row][tx] = W_post[(size_t)(row0 + row) * (RR + HH) + col0 + tx];
        }
        __syncthreads();
        #pragma unroll
        for (int r = 0; r < 4; ++r) {
            int row = ty0 + r * 8;
            int m = col0 + row;
            float v = tile[tx][row];
            if (m < RR) g_WphT[(size_t)m * LL + row0 + tx] = v;
            else        g_WpoT[(size_t)(m - RR) * LL + row0 + tx] = v;
        }
    }
}

// ---------------- obs GEMM: round-5 structure + register-staged prefetch ----------------
// out_logits[m][n] = b_post[n] + obs[m]·W_po[n].  M=32768, N=1024, K=256.
// 128x64 tile, BK=16, single smem buffer; next tile's LDGs issued between syncs
// so they overlap the 16-kk compute block.
__global__ void __launch_bounds__(256) obs_gemm(const float* __restrict__ obs,
                                                const float* __restrict__ b_post,
                                                float* __restrict__ outL) {
    __shared__ float2 As2[128][17];   // duplicated {a,a}
    __shared__ float  Bs[16][64];
    const int tid = threadIdx.x;
    const int bm = blockIdx.y * 128;
    const int bn = blockIdx.x * 64;
    const int ty = tid >> 4;
    const int tx = tid & 15;
    // A-load mapping (2 float4/thread): f = tid + i*256 -> row = f>>2, kp = (f&3)*4
    const int ar0 = tid >> 2,          akp0 = (tid & 3) * 4;
    const int ar1 = (tid + 256) >> 2,  akp1 = ((tid + 256) & 3) * 4;
    // B-load mapping (1 float4/thread): kk = tid>>4, n4 = (tid&15)*4
    const int bkk = tid >> 4;
    const int bn4 = (tid & 15) * 4;

    float2 acc2[8][2];
    #pragma unroll
    for (int i = 0; i < 8; ++i) { acc2[i][0] = make_float2(0.f, 0.f); acc2[i][1] = make_float2(0.f, 0.f); }

    // prologue: stage k0 = 0 in registers
    float4 va0 = *(const float4*)&obs[(size_t)(bm + ar0) * HH + akp0];
    float4 va1 = *(const float4*)&obs[(size_t)(bm + ar1) * HH + akp1];
    float4 vb  = *(const float4*)&g_WpoT[(size_t)bkk * LL + bn + bn4];

    #pragma unroll 1
    for (int k0 = 0; k0 < HH; k0 += 16) {
        // commit staged registers to smem
        As2[ar0][akp0 + 0] = make_float2(va0.x, va0.x);
        As2[ar0][akp0 + 1] = make_float2(va0.y, va0.y);
        As2[ar0][akp0 + 2] = make_float2(va0.z, va0.z);
        As2[ar0][akp0 + 3] = make_float2(va0.w, va0.w);
        As2[ar1][akp1 + 0] = make_float2(va1.x, va1.x);
        As2[ar1][akp1 + 1] = make_float2(va1.y, va1.y);
        As2[ar1][akp1 + 2] = make_float2(va1.z, va1.z);
        As2[ar1][akp1 + 3] = make_float2(va1.w, va1.w);
        *(float4*)&Bs[bkk][bn4] = vb;
        __syncthreads();

        // issue next tile's LDGs now — they complete under the compute block
        if (k0 + 16 < HH) {
            va0 = *(const float4*)&obs[(size_t)(bm + ar0) * HH + k0 + 16 + akp0];
            va1 = *(const float4*)&obs[(size_t)(bm + ar1) * HH + k0 + 16 + akp1];
            vb  = *(const float4*)&g_WpoT[(size_t)(k0 + 16 + bkk) * LL + bn + bn4];
        }

        // compute (identical to round-5 inner loop)
        #pragma unroll
        for (int kk = 0; kk < 16; ++kk) {
            float2 b0 = *(const float2*)&Bs[kk][tx * 4];
            float2 b1 = *(const float2*)&Bs[kk][tx * 4 + 2];
            #pragma unroll
            for (int i = 0; i < 8; ++i) {
                float2 a2 = As2[ty * 8 + i][kk];
                ffma2(acc2[i][0], a2, b0);
                ffma2(acc2[i][1], a2, b1);
            }
        }
        __syncthreads();
    }
    float bp0 = b_post[bn + tx * 4], bp1 = b_post[bn + tx * 4 + 1];
    float bp2 = b_post[bn + tx * 4 + 2], bp3 = b_post[bn + tx * 4 + 3];
    #pragma unroll
    for (int i = 0; i < 8; ++i) {
        int m = bm + ty * 8 + i;
        float4 v;
        v.x = acc2[i][0].x + bp0; v.y = acc2[i][0].y + bp1;
        v.z = acc2[i][1].x + bp2; v.w = acc2[i][1].y + bp3;
        *(float4*)&outL[(size_t)m * LL + bn + tx * 4] = v;
    }
}

// ---------------- cluster-2 persistent scan (round-9/11 proven version, verbatim) ----------------
#define OFF_GI     0
#define OFF_GH8    3072
#define OFF_GHR    9216
#define OFF_DET8   12288
#define OFF_DETOWN 16384
#define OFF_LG8    18432
#define OFF_LGR    26624
#define SMEM_FLOATS 30720

__global__ void __launch_bounds__(512, 1) __cluster_dims__(2, 1, 1)
scan_kernel(const float* __restrict__ action,
            const unsigned int* __restrict__ first,
            const float* __restrict__ gumbel,       // [T][B][1024]
            const float* __restrict__ b_hh,
            float* __restrict__ out) {

    extern __shared__ float smem[];
    float* s_gi     = smem + OFF_GI;
    float* s_gh8    = smem + OFF_GH8;
    float* s_ghr    = smem + OFF_GHR;
    float* s_det8   = smem + OFF_DET8;
    float* s_detown = smem + OFF_DETOWN;
    float* s_lg8    = smem + OFF_LG8;
    float* s_lgr    = smem + OFF_LGR;
    __shared__ int   s_idx[4][32];
    __shared__ float s_act[4][AA];
    __shared__ int   s_reset[8];     // pair-global rows, first[t]

    cg::cluster_group cluster = cg::this_cluster();
    const int rank = (int)cluster.block_rank();
    float* p_ghr  = (float*)cluster.map_shared_rank(s_ghr,  rank ^ 1);
    float* p_det8 = (float*)cluster.map_shared_rank(s_det8, rank ^ 1);
    float* p_lgr  = (float*)cluster.map_shared_rank(s_lgr,  rank ^ 1);

    const int tid = threadIdx.x;
    const int jh  = tid >> 8;        // intra-CTA jj-half
    const int lk  = tid & 255;
    const int pair  = blockIdx.x >> 1;
    const int prow0 = pair * 8;
    const int orow0 = prow0 + rank * 4;      // own rows base
    const int Jbase = rank * 128;            // this CTA's j slice
    int cur = 0;

    for (int t = 0; t < TT; ++t) {
        // ---- flags (all 8 rows) + action (own rows) ----
        if (tid < 8) {
            unsigned f = first[(prow0 + tid) * TT + t];
            s_reset[tid] = (t == 0) || (f != 0u);
        }
        if (tid >= 32 && tid < 32 + 4 * AA) {
            int e = tid - 32;
            s_act[e / AA][e % AA] = action[((size_t)(orow0 + e / AA) * TT + t) * AA + (e % AA)];
        }
        __syncthreads();

        // ---- zero carries on reset (det8 slice: all 8 rows; detown: own rows) ----
        #pragma unroll
        for (int k = 0; k < 2; ++k) {
            int idx = tid + k * 512;       // 1024 items: det8 slice
            int jj = idx >> 3, g = idx & 7;
            if (s_reset[g])
                *(float2*)&s_det8[cur * 2048 + jj * 16 + 2 * g] = make_float2(0.f, 0.f);
        }
        #pragma unroll
        for (int k = 0; k < 2; ++k) {
            int idx = tid + k * 512;       // 1024 items: detown
            int r = idx >> 8, u = idx & 255;
            if (s_reset[rank * 4 + r])
                s_detown[cur * 1024 + r * 256 + u] = 0.f;
        }
        __syncthreads();

        // ---- gi for own rows (bias + action + one-hot gather) ----
        for (int item = tid; item < 4 * 192; item += 512) {
            int r = item / 192;
            int q = (item % 192) * 4;
            float4 a4 = *(const float4*)&g_bc[q];
            #pragma unroll
            for (int j = 0; j < AA; ++j) {
                float av = s_act[r][j];
                float4 w = *(const float4*)&g_WcaT[j * KG + q];
                a4.x = fmaf(av, w.x, a4.x); a4.y = fmaf(av, w.y, a4.y);
                a4.z = fmaf(av, w.z, a4.z); a4.w = fmaf(av, w.w, a4.w);
            }
            if (!s_reset[rank * 4 + r]) {
                #pragma unroll 8
                for (int g = 0; g < 32; ++g) {
                    int c = (g << 5) + s_idx[r][g];
                    float4 w = *(const float4*)&g_WcT[c * KG + q];
                    a4.x += w.x; a4.y += w.y; a4.z += w.z; a4.w += w.w;
                }
            }
            *(float4*)&s_gi[r * KG + q] = a4;
        }

        // ---- phase 1: gh partial over my j-slice (8-deep weight prefetch) ----
        float2 gh[8][2];
        if (lk < 192) {
            const int q4 = lk * 4;
            if (rank == 0 && jh == 0) {
                float4 bh = *(const float4*)&b_hh[q4];
                #pragma unroll
                for (int g = 0; g < 8; ++g) {
                    gh[g][0] = make_float2(bh.x, bh.y);
                    gh[g][1] = make_float2(bh.z, bh.w);
                }
            } else {
                #pragma unroll
                for (int g = 0; g < 8; ++g) {
                    gh[g][0] = make_float2(0.f, 0.f);
                    gh[g][1] = make_float2(0.f, 0.f);
                }
            }
            const float4* wp  = (const float4*)&g_WhhT[(size_t)(Jbase + jh * 64) * KG + q4];
            const size_t  WS  = KG / 4;
            const float4* db4 = (const float4*)(s_det8 + cur * 2048 + (jh * 64) * 16);
            float4 wb8[8];
            #pragma unroll
            for (int p = 0; p < 8; ++p) wb8[p] = wp[(size_t)p * WS];
            #pragma unroll 1
            for (int base = 0; base < 64; base += 8) {
                #pragma unroll
                for (int p = 0; p < 8; ++p) {
                    float4 w = wb8[p];
                    int nj = base + 8 + p; nj = (nj < 64) ? nj : 63;
                    wb8[p] = wp[(size_t)nj * WS];
                    const float4* dq = db4 + (size_t)(base + p) * 4;
                    float4 dA = dq[0], dB = dq[1], dC = dq[2], dD = dq[3];
                    float2 wl = make_float2(w.x, w.y), wh2 = make_float2(w.z, w.w);
                    float2 dp[8] = { make_float2(dA.x, dA.y), make_float2(dA.z, dA.w),
                                     make_float2(dB.x, dB.y), make_float2(dB.z, dB.w),
                                     make_float2(dC.x, dC.y), make_float2(dC.z, dC.w),
                                     make_float2(dD.x, dD.y), make_float2(dD.z, dD.w) };
                    #pragma unroll
                    for (int g = 0; g < 8; ++g) {
                        ffma2(gh[g][0], dp[g], wl);
                        ffma2(gh[g][1], dp[g], wh2);
                    }
                }
            }
            if (jh == 0) {
                #pragma unroll
                for (int g = 0; g < 8; ++g)
                    *(float4*)&s_gh8[g * KG + q4] =
                        make_float4(gh[g][0].x, gh[g][0].y, gh[g][1].x, gh[g][1].y);
            }
        }
        __syncthreads();
        if (jh == 1 && lk < 192) {   // combine halves; push peer rows to peer's s_ghr
            const int q4 = lk * 4;
            const int pb = (rank ^ 1) * 4;
            #pragma unroll
            for (int g = 0; g < 8; ++g) {
                float4 p = *(const float4*)&s_gh8[g * KG + q4];
                float4 c = make_float4(p.x + gh[g][0].x, p.y + gh[g][0].y,
                                       p.z + gh[g][1].x, p.w + gh[g][1].y);
                *(float4*)&s_gh8[g * KG + q4] = c;
                if (g >= pb && g < pb + 4)
                    *(float4*)&p_ghr[(g - pb) * KG + q4] = c;
            }
        }
        cluster.sync();   // CS1: gh partials exchanged

        // ---- GRU for own rows + det distribution ----
        {
            const int u = lk;
            #pragma unroll
            for (int ii = 0; ii < 2; ++ii) {
                int i = jh * 2 + ii;          // own-local row
                int g = rank * 4 + i;         // pair-global row
                float ir = s_gi[i * KG + u];
                float hr = s_gh8[g * KG + u]       + s_ghr[i * KG + u];
                float iz = s_gi[i * KG + u + 256];
                float hz = s_gh8[g * KG + u + 256] + s_ghr[i * KG + u + 256];
                float in_ = s_gi[i * KG + u + 512];
                float hn = s_gh8[g * KG + u + 512] + s_ghr[i * KG + u + 512];
                float rg = 1.f / (1.f + expf(-(ir + hr)));
                float z  = 1.f / (1.f + expf(-(iz + hz)));
                float n  = tanhf(fmaf(rg, hn, in_));
                float dp = s_detown[cur * 1024 + i * 256 + u];
                float h  = (1.f - z) * n + z * dp;
                s_detown[(cur ^ 1) * 1024 + i * 256 + u] = h;
                float2 hh = make_float2(h, h);
                int jloc = u & 127;
                if ((u >> 7) == rank)
                    *(float2*)&s_det8[(cur ^ 1) * 2048 + jloc * 16 + 2 * g] = hh;
                else
                    *(float2*)&p_det8[(cur ^ 1) * 2048 + jloc * 16 + 2 * g] = hh;
                out[DET_OFF + ((size_t)(orow0 + i) * TT + t) * RR + u] = h;
            }
        }
        cluster.sync();   // CS2: new det slices exchanged

        // ---- phase 2: logits partial over my j-slice (8-deep weight prefetch) ----
        float2 acc[8][2];
        {
            const int q4 = lk * 4;
            #pragma unroll
            for (int g = 0; g < 8; ++g) {
                acc[g][0] = make_float2(0.f, 0.f);
                acc[g][1] = make_float2(0.f, 0.f);
            }
            const float4* wp  = (const float4*)&g_WphT[(size_t)(Jbase + jh * 64) * LL + q4];
            const size_t  WS  = LL / 4;
            const float4* db4 = (const float4*)(s_det8 + (cur ^ 1) * 2048 + (jh * 64) * 16);
            float4 wb8[8];
            #pragma unroll
            for (int p = 0; p < 8; ++p) wb8[p] = wp[(size_t)p * WS];
            #pragma unroll 1
            for (int base = 0; base < 64; base += 8) {
                #pragma unroll
                for (int p = 0; p < 8; ++p) {
                    float4 w = wb8[p];
                    int nj = base + 8 + p; nj = (nj < 64) ? nj : 63;
                    wb8[p] = wp[(size_t)nj * WS];
                    const float4* dq = db4 + (size_t)(base + p) * 4;
                    float4 dA = dq[0], dB = dq[1], dC = dq[2], dD = dq[3];
                    float2 wl = make_float2(w.x, w.y), wh2 = make_float2(w.z, w.w);
                    float2 dp[8] = { make_float2(dA.x, dA.y), make_float2(dA.z, dA.w),
                                     make_float2(dB.x, dB.y), make_float2(dB.z, dB.w),
                                     make_float2(dC.x, dC.y), make_float2(dC.z, dC.w),
                                     make_float2(dD.x, dD.y), make_float2(dD.z, dD.w) };
                    #pragma unroll
                    for (int g = 0; g < 8; ++g) {
                        ffma2(acc[g][0], dp[g], wl);
                        ffma2(acc[g][1], dp[g], wh2);
                    }
                }
            }
            if (jh == 0) {
                #pragma unroll
                for (int g = 0; g < 8; ++g)
                    *(float4*)&s_lg8[g * LL + q4] =
                        make_float4(acc[g][0].x, acc[g][0].y, acc[g][1].x, acc[g][1].y);
            }
        }
        __syncthreads();
        if (jh == 1) {
            const int q4 = lk * 4;
            const int pb = (rank ^ 1) * 4;
            #pragma unroll
            for (int g = 0; g < 8; ++g) {
                float4 p = *(const float4*)&s_lg8[g * LL + q4];
                float4 c = make_float4(p.x + acc[g][0].x, p.y + acc[g][0].y,
                                       p.z + acc[g][1].x, p.w + acc[g][1].y);
                *(float4*)&s_lg8[g * LL + q4] = c;
                if (g >= pb && g < pb + 4)
                    *(float4*)&p_lgr[(g - pb) * LL + q4] = c;
            }
        }
        cluster.sync();   // CS3: logits partials exchanged

        // ---- finalize own rows: logits, gumbel argmax, one-hot stoch ----
        {
            const int q4 = lk * 4;
            #pragma unroll
            for (int ii = 0; ii < 2; ++ii) {
                int i = jh * 2 + ii;
                int g = rank * 4 + i;
                size_t bt = (size_t)(orow0 + i) * TT + t;
                float4 ob = *(const float4*)&out[LG_OFF + bt * LL + q4];  // obs part + b_post
                float4 pa = *(const float4*)&s_lg8[g * LL + q4];
                float4 pbv = *(const float4*)&s_lgr[i * LL + q4];
                float4 lg;
                lg.x = ob.x + pa.x + pbv.x; lg.y = ob.y + pa.y + pbv.y;
                lg.z = ob.z + pa.z + pbv.z; lg.w = ob.w + pa.w + pbv.w;
                *(float4*)&out[LG_OFF + bt * LL + q4] = lg;
                float4 g4 = *(const float4*)&gumbel[((size_t)t * BB + orow0 + i) * LL + q4];
                float v0 = lg.x + g4.x, v1 = lg.y + g4.y;
                float v2 = lg.z + g4.z, v3 = lg.w + g4.w;
                float bv = v0; int bi = q4;
                if (v1 > bv) { bv = v1; bi = q4 + 1; }
                if (v2 > bv) { bv = v2; bi = q4 + 2; }
                if (v3 > bv) { bv = v3; bi = q4 + 3; }
                #pragma unroll
                for (int off = 1; off < 8; off <<= 1) {
                    float ov = __shfl_xor_sync(0xffffffffu, bv, off);
                    int   oi = __shfl_xor_sync(0xffffffffu, bi, off);
                    if (ov > bv || (ov == bv && oi < bi)) { bv = ov; bi = oi; }
                }
                float4 sv;
                sv.x = (q4 + 0 == bi) ? 1.f : 0.f;
                sv.y = (q4 + 1 == bi) ? 1.f : 0.f;
                sv.z = (q4 + 2 == bi) ? 1.f : 0.f;
                sv.w = (q4 + 3 == bi) ? 1.f : 0.f;
                *(float4*)&out[ST_OFF + bt * LL + q4] = sv;
                if ((lk & 7) == 0) s_idx[i][lk >> 3] = bi & 31;
            }
        }
        cur ^= 1;
    }
}

// ---------------- launcher ----------------
extern "C" void kernel_launch(void* const* d_in, const int* in_sizes, int n_in,
                              void* d_out, int out_size) {
    const float* obs          = (const float*)d_in[0];
    const float* action       = (const float*)d_in[1];
    const unsigned int* first = (const unsigned int*)d_in[2];
    const float* gumbel       = (const float*)d_in[3];
    const float* W_in         = (const float*)d_in[4];
    const float* b_in         = (const float*)d_in[5];
    const float* W_ih         = (const float*)d_in[6];
    const float* W_hh         = (const float*)d_in[7];
    const float* b_ih         = (const float*)d_in[8];
    const float* b_hh         = (const float*)d_in[9];
    const float* W_post       = (const float*)d_in[10];
    const float* b_post       = (const float*)d_in[11];
    float* out = (float*)d_out;
    (void)in_sizes; (void)n_in; (void)out_size;

    static int smem_set = 0;
    if (!smem_set) {
        cudaFuncSetAttribute(scan_kernel, cudaFuncAttributeMaxDynamicSharedMemorySize,
                             SMEM_FLOATS * sizeof(float));
        smem_set = 1;
    }

    prep_fuse<<<dim3(KG / 64, 17), 256>>>(W_in, b_in, W_ih, b_ih);
    prep_transpose<<<dim3(32, 16, 2), 256>>>(W_hh, W_post);
    dim3 ggrid(LL / 64, (BB * TT) / 128);
    obs_gemm<<<ggrid, 256>>>(obs, b_post, out + LG_OFF);
    scan_kernel<<<NCTA, 512, SMEM_FLOATS * sizeof(float)>>>(action, first, gumbel, b_hh, out);
}